// round 3
// baseline (speedup 1.0000x reference)
#include <cuda_runtime.h>

#define FULLMASK 0xffffffffu

constexpr int T_ = 256;
constexpr int C_ = 128;
constexpr int L_ = 32;
constexpr int BLANK = 127;   // C-1
constexpr float EPSF = 1e-7f;

// Warp-per-batch-element CTC forward (alpha) in probability domain with
// per-step rescaling. Alphas in fp64 (range safety), probs/scales in fp32.
// Lane i owns states s=i (aLo) and s=32+i (aHi); lane 31 also owns s=64 (aTop).
__global__ __launch_bounds__(128, 8)
void ctc_alpha_kernel(const int* __restrict__ y_true_i32,
                      const float* __restrict__ y_pred,
                      float* __restrict__ out)
{
    const int warp = threadIdx.x >> 5;
    const int lane = threadIdx.x & 31;
    const int b    = blockIdx.x * 4 + warp;

    __shared__ float sh[4][2][C_];   // per-warp double-buffered prob row

    const float* rowbase = y_pred + (size_t)b * T_ * C_;

    // ---- label dtype detection: words 0..31 are in-bounds for int32 or int64.
    // int64 little-endian with labels < 2^31 => all odd i32 words are zero.
    int w0 = y_true_i32[lane];
    unsigned zmask = __ballot_sync(FULLMASK, w0 == 0);
    bool is64 = ((zmask & 0xAAAAAAAAu) == 0xAAAAAAAAu);

    int myLab;
    if (is64) myLab = y_true_i32[((size_t)b * L_ + lane) * 2];  // low word
    else      myLab = y_true_i32[(size_t)b * L_ + lane];
    myLab &= 127;   // safety clamp: gather index must stay in [0,127]

    // ---- extended-label class + skip permission, computed once.
    // Lo states: s = lane. Odd s are labels: ext = lab[(s-1)/2].
    int  kLo      = (lane >= 1) ? ((lane - 1) >> 1) : 0;
    int  labLo    = __shfl_sync(FULLMASK, myLab, kLo);
    int  labLoPrv = __shfl_sync(FULLMASK, myLab, (kLo >= 1) ? (kLo - 1) : 0);
    bool odd      = (lane & 1);
    int  extLo    = odd ? labLo : BLANK;
    double skipLo = (odd && lane >= 3 && labLo != labLoPrv) ? 1.0 : 0.0;

    // Hi states: s = 32 + lane (same parity as lane). label idx = (31+lane)/2.
    int  kHi      = (31 + lane) >> 1;
    int  labHi    = __shfl_sync(FULLMASK, myLab, kHi);
    int  labHiPrv = __shfl_sync(FULLMASK, myLab, (kHi >= 1) ? (kHi - 1) : 0);
    int  extHi    = odd ? labHi : BLANK;
    double skipHi = (odd && labHi != labHiPrv) ? 1.0 : 0.0;  // s>=33 → always >=3

    // ---- t = 0 init
    {
        float4 v0 = ((const float4*)rowbase)[lane];
        ((float4*)sh[warp][0])[lane] = v0;
    }
    __syncwarp();

    double aLo = 0.0, aHi = 0.0, aTop = 0.0;
    {
        const float* r0 = sh[warp][0];
        if (lane == 0) aLo = (double)(r0[BLANK] + EPSF);
        if (lane == 1) aLo = (double)(r0[extLo] + EPSF);
    }

    // initial scale s0
    double part = aLo;
    #pragma unroll
    for (int d = 16; d; d >>= 1) part += __shfl_xor_sync(FULLMASK, part, d);
    float s0      = (float)part;
    float acc     = __logf(s0);
    float invCur  = 1.0f;                    // applied at iter t (deferred by 2)
    float invNext = __fdividef(1.0f, s0);    // applied at iter t+1

    // ---- 3-deep prefetch pipeline for prob rows
    float4 p1 = ((const float4*)(rowbase + (size_t)1 * C_))[lane];
    float4 p2 = ((const float4*)(rowbase + (size_t)2 * C_))[lane];
    float4 p3 = ((const float4*)(rowbase + (size_t)3 * C_))[lane];

    #pragma unroll 2
    for (int t = 1; t < T_; ++t) {
        float* buf = sh[warp][t & 1];
        ((float4*)buf)[lane] = p1;
        p1 = p2; p2 = p3;
        int tn = (t + 3 < T_) ? (t + 3) : (T_ - 1);
        p3 = ((const float4*)(rowbase + (size_t)tn * C_))[lane];
        __syncwarp();

        // gather emission probs for my 3 states (deferred normalization folded in)
        float pLo  = (buf[extLo] + EPSF) * invCur;
        float pHi  = (buf[extHi] + EPSF) * invCur;
        float pTop = (buf[BLANK] + EPSF) * invCur;

        // neighbor shifts
        double lo1 = __shfl_up_sync(FULLMASK, aLo, 1);
        double lo2 = __shfl_up_sync(FULLMASK, aLo, 2);
        double l31 = __shfl_sync(FULLMASK, aLo, 31);
        double l30 = __shfl_sync(FULLMASK, aLo, 30);
        double hi1 = __shfl_up_sync(FULLMASK, aHi, 1);
        double hi2 = __shfl_up_sync(FULLMASK, aHi, 2);
        if (lane == 0) { lo1 = 0.0; lo2 = 0.0; hi1 = l31; hi2 = l30; }
        if (lane == 1) { lo2 = 0.0; hi2 = l31; }

        double nLo  = (aLo + lo1 + skipLo * lo2) * (double)pLo;
        double nHi  = (aHi + hi1 + skipHi * hi2) * (double)pHi;
        double nTop = (aTop + aHi) * (double)pTop;   // s=64 (blank): no skip; valid on lane 31
        aLo = nLo; aHi = nHi; aTop = nTop;

        // rescale bookkeeping (reduce result only needed 2 iterations later)
        if (t < T_ - 2) {
            double p2r = nLo + nHi + ((lane == 31) ? nTop : 0.0);
            #pragma unroll
            for (int d = 16; d; d >>= 1) p2r += __shfl_xor_sync(FULLMASK, p2r, d);
            float s = (float)p2r;
            acc += __logf(s);
            invCur  = invNext;
            invNext = __fdividef(1.0f, s);
        } else {
            invCur = invNext;   // t = T-2: last pending inv applies at t = T-1
        }
    }

    // loss = -( log(alpha[S-1] + alpha[S-2]) + sum of applied log-scales )
    if (lane == 31) {
        float fin = (float)(aTop + aHi);
        out[b] = -(__logf(fin) + acc);
    }
}

extern "C" void kernel_launch(void* const* d_in, const int* in_sizes, int n_in,
                              void* d_out, int out_size) {
    // Identify inputs by size: y_true has B*L elements, y_pred has B*T*C.
    int idx_small = 0, idx_big = 1;
    if (in_sizes[0] > in_sizes[1]) { idx_small = 1; idx_big = 0; }

    const int*   y_true = (const int*)d_in[idx_small];   // int32 view; width detected in-kernel
    const float* y_pred = (const float*)d_in[idx_big];
    float*       out    = (float*)d_out;

    int B = in_sizes[idx_big] / (T_ * C_);   // 1024
    int blocks = B / 4;                      // 4 warps (batch elements) per block
    ctc_alpha_kernel<<<blocks, 128>>>(y_true, y_pred, out);
}

// round 4
// speedup vs baseline: 2.2559x; 2.2559x over previous
#include <cuda_runtime.h>

#define FULLMASK 0xffffffffu

constexpr int T_ = 256;
constexpr int C_ = 128;
constexpr int L_ = 32;
constexpr int BLANK = 127;   // C-1
constexpr float EPSF = 1e-7f;
constexpr int EPW = 2;       // batch elements per warp (ILP)

// Warp-per-2-batch-elements CTC forward (alpha) in probability domain with
// periodic (every 4 steps) rescaling, all fp32.
// Lane i owns states s=i (aLo) and s=32+i (aHi); lane 31 also owns s=64 (aTop).
__global__ __launch_bounds__(128)
void ctc_alpha_kernel(const int* __restrict__ y_true_i32,
                      const float* __restrict__ y_pred,
                      float* __restrict__ out)
{
    const int warp = threadIdx.x >> 5;
    const int lane = threadIdx.x & 31;
    const int b0   = (blockIdx.x * 4 + warp) * EPW;
    const int b1   = b0 + 1;

    __shared__ float sh[4][2][EPW][C_];   // per-warp double-buffered prob rows

    const float* row0 = y_pred + (size_t)b0 * T_ * C_;
    const float* row1 = y_pred + (size_t)b1 * T_ * C_;

    // ---- label dtype detection (int32 vs int64 low-word), in-bounds either way
    int w0 = y_true_i32[lane];
    unsigned zmask = __ballot_sync(FULLMASK, w0 == 0);
    bool is64 = ((zmask & 0xAAAAAAAAu) == 0xAAAAAAAAu);

    int lab0 = is64 ? y_true_i32[((size_t)b0 * L_ + lane) * 2]
                    : y_true_i32[(size_t)b0 * L_ + lane];
    int lab1 = is64 ? y_true_i32[((size_t)b1 * L_ + lane) * 2]
                    : y_true_i32[(size_t)b1 * L_ + lane];
    lab0 &= 127; lab1 &= 127;

    // ---- extended-label class + skip permission (per element)
    const bool odd = (lane & 1);
    const int  kLo = (lane >= 1) ? ((lane - 1) >> 1) : 0;
    const int  kLp = (kLo >= 1) ? (kLo - 1) : 0;
    const int  kHi = (31 + lane) >> 1;
    const int  kHp = kHi - 1;   // kHi >= 15 always

    int labLo0 = __shfl_sync(FULLMASK, lab0, kLo);
    int labLp0 = __shfl_sync(FULLMASK, lab0, kLp);
    int labHi0 = __shfl_sync(FULLMASK, lab0, kHi);
    int labHp0 = __shfl_sync(FULLMASK, lab0, kHp);
    int labLo1 = __shfl_sync(FULLMASK, lab1, kLo);
    int labLp1 = __shfl_sync(FULLMASK, lab1, kLp);
    int labHi1 = __shfl_sync(FULLMASK, lab1, kHi);
    int labHp1 = __shfl_sync(FULLMASK, lab1, kHp);

    const int   extLo0  = odd ? labLo0 : BLANK;
    const int   extHi0  = odd ? labHi0 : BLANK;
    const float skipLo0 = (odd && lane >= 3 && labLo0 != labLp0) ? 1.0f : 0.0f;
    const float skipHi0 = (odd && labHi0 != labHp0) ? 1.0f : 0.0f;
    const int   extLo1  = odd ? labLo1 : BLANK;
    const int   extHi1  = odd ? labHi1 : BLANK;
    const float skipLo1 = (odd && lane >= 3 && labLo1 != labLp1) ? 1.0f : 0.0f;
    const float skipHi1 = (odd && labHi1 != labHp1) ? 1.0f : 0.0f;

    // ---- t = 0 init (stage row 0 through smem for the 2 gathers)
    ((float4*)sh[warp][0][0])[lane] = ((const float4*)row0)[lane];
    ((float4*)sh[warp][0][1])[lane] = ((const float4*)row1)[lane];
    __syncwarp();

    float aLo0 = 0.f, aHi0 = 0.f, aTop0 = 0.f;
    float aLo1 = 0.f, aHi1 = 0.f, aTop1 = 0.f;
    if (lane == 0) { aLo0 = sh[warp][0][0][BLANK] + EPSF;  aLo1 = sh[warp][0][1][BLANK] + EPSF; }
    if (lane == 1) { aLo0 = sh[warp][0][0][extLo0] + EPSF; aLo1 = sh[warp][0][1][extLo1] + EPSF; }

    float r0 = aLo0, r1 = aLo1;
    #pragma unroll
    for (int d = 16; d; d >>= 1) {
        r0 += __shfl_xor_sync(FULLMASK, r0, d);
        r1 += __shfl_xor_sync(FULLMASK, r1, d);
    }
    float acc0 = __logf(r0),               acc1 = __logf(r1);
    float pend0 = __fdividef(1.0f, r0),    pend1 = __fdividef(1.0f, r1);

    // ---- 3-deep float4 prefetch pipeline (both elements)
    float4 p1a = ((const float4*)(row0 + (size_t)1 * C_))[lane];
    float4 p1b = ((const float4*)(row1 + (size_t)1 * C_))[lane];
    float4 p2a = ((const float4*)(row0 + (size_t)2 * C_))[lane];
    float4 p2b = ((const float4*)(row1 + (size_t)2 * C_))[lane];
    float4 p3a = ((const float4*)(row0 + (size_t)3 * C_))[lane];
    float4 p3b = ((const float4*)(row1 + (size_t)3 * C_))[lane];

    for (int t = 1; t < T_; ++t) {
        float* buf0 = sh[warp][t & 1][0];
        float* buf1 = sh[warp][t & 1][1];
        ((float4*)buf0)[lane] = p1a;
        ((float4*)buf1)[lane] = p1b;
        p1a = p2a; p2a = p3a;
        p1b = p2b; p2b = p3b;
        int tn = (t + 3 < T_) ? (t + 3) : (T_ - 1);
        p3a = ((const float4*)(row0 + (size_t)tn * C_))[lane];
        p3b = ((const float4*)(row1 + (size_t)tn * C_))[lane];
        __syncwarp();

        // scale application: pending inv applied at t % 4 == 2, else identity
        float ic = ((t & 3) == 2) ? 1.0f : 1.0f;   // placeholder, split per elem below
        float ic0 = ((t & 3) == 2) ? pend0 : 1.0f;
        float ic1 = ((t & 3) == 2) ? pend1 : 1.0f;
        (void)ic;
        float e0 = EPSF * ic0, e1 = EPSF * ic1;

        float pLo0 = fmaf(buf0[extLo0], ic0, e0);
        float pHi0 = fmaf(buf0[extHi0], ic0, e0);
        float pTp0 = fmaf(buf0[BLANK],  ic0, e0);
        float pLo1 = fmaf(buf1[extLo1], ic1, e1);
        float pHi1 = fmaf(buf1[extHi1], ic1, e1);
        float pTp1 = fmaf(buf1[BLANK],  ic1, e1);

        // neighbor shifts (fp32: single shfl each)
        float lo1a = __shfl_up_sync(FULLMASK, aLo0, 1);
        float lo2a = __shfl_up_sync(FULLMASK, aLo0, 2);
        float t31a = __shfl_sync(FULLMASK, aLo0, 31);
        float t30a = __shfl_sync(FULLMASK, aLo0, 30);
        float hi1a = __shfl_up_sync(FULLMASK, aHi0, 1);
        float hi2a = __shfl_up_sync(FULLMASK, aHi0, 2);
        float lo1b = __shfl_up_sync(FULLMASK, aLo1, 1);
        float lo2b = __shfl_up_sync(FULLMASK, aLo1, 2);
        float t31b = __shfl_sync(FULLMASK, aLo1, 31);
        float t30b = __shfl_sync(FULLMASK, aLo1, 30);
        float hi1b = __shfl_up_sync(FULLMASK, aHi1, 1);
        float hi2b = __shfl_up_sync(FULLMASK, aHi1, 2);
        if (lane == 0) { lo1a = 0.f; lo2a = 0.f; hi1a = t31a; hi2a = t30a;
                         lo1b = 0.f; lo2b = 0.f; hi1b = t31b; hi2b = t30b; }
        if (lane == 1) { lo2a = 0.f; hi2a = t31a;
                         lo2b = 0.f; hi2b = t31b; }

        float nLo0 = fmaf(skipLo0, lo2a, aLo0 + lo1a) * pLo0;
        float nHi0 = fmaf(skipHi0, hi2a, aHi0 + hi1a) * pHi0;
        float nTp0 = (aTop0 + aHi0) * pTp0;
        float nLo1 = fmaf(skipLo1, lo2b, aLo1 + lo1b) * pLo1;
        float nHi1 = fmaf(skipHi1, hi2b, aHi1 + hi1b) * pHi1;
        float nTp1 = (aTop1 + aHi1) * pTp1;
        aLo0 = nLo0; aHi0 = nHi0; aTop0 = nTp0;
        aLo1 = nLo1; aHi1 = nHi1; aTop1 = nTp1;

        // periodic rescale: reduce at t % 4 == 0 (result applied at t+2)
        if ((t & 3) == 0) {
            float s0 = nLo0 + nHi0 + ((lane == 31) ? nTp0 : 0.f);
            float s1 = nLo1 + nHi1 + ((lane == 31) ? nTp1 : 0.f);
            #pragma unroll
            for (int d = 16; d; d >>= 1) {
                s0 += __shfl_xor_sync(FULLMASK, s0, d);
                s1 += __shfl_xor_sync(FULLMASK, s1, d);
            }
            acc0 += __logf(s0);
            acc1 += __logf(s1);
            pend0 = __fdividef(1.0f, s0);
            pend1 = __fdividef(1.0f, s1);
        }
    }

    // loss = -( log(alpha[S-1] + alpha[S-2]) + sum of applied log-scales )
    if (lane == 31) {
        out[b0] = -(__logf(aTop0 + aHi0) + acc0);
        out[b1] = -(__logf(aTop1 + aHi1) + acc1);
    }
}

extern "C" void kernel_launch(void* const* d_in, const int* in_sizes, int n_in,
                              void* d_out, int out_size) {
    // Identify inputs by size: y_true has B*L elements, y_pred has B*T*C.
    int idx_small = 0, idx_big = 1;
    if (in_sizes[0] > in_sizes[1]) { idx_small = 1; idx_big = 0; }

    const int*   y_true = (const int*)d_in[idx_small];   // int32 view; width detected in-kernel
    const float* y_pred = (const float*)d_in[idx_big];
    float*       out    = (float*)d_out;

    int B = in_sizes[idx_big] / (T_ * C_);   // 1024
    int blocks = B / (4 * EPW);              // 4 warps x 2 elements per block
    ctc_alpha_kernel<<<blocks, 128>>>(y_true, y_pred, out);
}

// round 5
// speedup vs baseline: 10.5093x; 4.6586x over previous
#include <cuda_runtime.h>
#include <cstdint>

#define FULLMASK 0xffffffffu

constexpr int T_ = 256;
constexpr int C_ = 128;
constexpr int L_ = 32;
constexpr int BLANK = 127;   // C-1
constexpr float EPSF = 1e-7f;
constexpr int EPW = 2;       // batch elements per warp (ILP)
constexpr int DEPTH = 8;     // cp.async ring depth

__device__ __forceinline__ uint32_t smem_u32(const void* p) {
    uint32_t a;
    asm("{ .reg .u64 t; cvta.to.shared.u64 t, %1; cvt.u32.u64 %0, t; }"
        : "=r"(a) : "l"(p));
    return a;
}
__device__ __forceinline__ void cp16(uint32_t dst, const float* src) {
    asm volatile("cp.async.cg.shared.global [%0], [%1], 16;"
                 :: "r"(dst), "l"(src) : "memory");
}
#define CP_COMMIT() asm volatile("cp.async.commit_group;" ::: "memory")
#define CP_WAIT7()  asm volatile("cp.async.wait_group 7;" ::: "memory")

// One warp per block; each warp owns 2 batch elements.
// Lane i owns states s=i (aLo) and s=32+i (aHi); lane 31 also owns s=64 (aTop).
// Probability-domain alphas (fp32) with every-4-step rescaling, applied deferred.
__global__ __launch_bounds__(32)
void ctc_alpha_kernel(const int* __restrict__ y_true_i32,
                      const float* __restrict__ y_pred,
                      float* __restrict__ out)
{
    const int lane = threadIdx.x;          // blockDim.x == 32
    const int b0   = blockIdx.x * EPW;
    const int b1   = b0 + 1;

    __shared__ float ring[DEPTH][EPW][C_];   // 8KB ring of prob rows
    const uint32_t ring_base = smem_u32(&ring[0][0][0]);

    const float* row0 = y_pred + (size_t)b0 * T_ * C_;
    const float* row1 = y_pred + (size_t)b1 * T_ * C_;

    // ---- label dtype detection (int32 vs int64 low-word); first 32 words in-bounds
    int w0 = y_true_i32[lane];
    unsigned zmask = __ballot_sync(FULLMASK, w0 == 0);
    bool is64 = ((zmask & 0xAAAAAAAAu) == 0xAAAAAAAAu);

    int lab0 = is64 ? y_true_i32[((size_t)b0 * L_ + lane) * 2]
                    : y_true_i32[(size_t)b0 * L_ + lane];
    int lab1 = is64 ? y_true_i32[((size_t)b1 * L_ + lane) * 2]
                    : y_true_i32[(size_t)b1 * L_ + lane];
    lab0 &= 127; lab1 &= 127;

    // ---- extended-label class + skip permission
    const bool odd = (lane & 1);
    const int  kLo = (lane >= 1) ? ((lane - 1) >> 1) : 0;
    const int  kLp = (kLo >= 1) ? (kLo - 1) : 0;
    const int  kHi = (31 + lane) >> 1;
    const int  kHp = kHi - 1;

    int labLo0 = __shfl_sync(FULLMASK, lab0, kLo);
    int labLp0 = __shfl_sync(FULLMASK, lab0, kLp);
    int labHi0 = __shfl_sync(FULLMASK, lab0, kHi);
    int labHp0 = __shfl_sync(FULLMASK, lab0, kHp);
    int labLo1 = __shfl_sync(FULLMASK, lab1, kLo);
    int labLp1 = __shfl_sync(FULLMASK, lab1, kLp);
    int labHi1 = __shfl_sync(FULLMASK, lab1, kHi);
    int labHp1 = __shfl_sync(FULLMASK, lab1, kHp);

    const int   extLo0  = odd ? labLo0 : BLANK;
    const int   extHi0  = odd ? labHi0 : BLANK;
    const float skipLo0 = (odd && lane >= 3 && labLo0 != labLp0) ? 1.0f : 0.0f;
    const float skipHi0 = (odd && labHi0 != labHp0) ? 1.0f : 0.0f;
    const int   extLo1  = odd ? labLo1 : BLANK;
    const int   extHi1  = odd ? labHi1 : BLANK;
    const float skipLo1 = (odd && lane >= 3 && labLo1 != labLp1) ? 1.0f : 0.0f;
    const float skipHi1 = (odd && labHi1 != labHp1) ? 1.0f : 0.0f;

    // ---- prologue: fill ring with rows 1..8 (one commit group per row)
    #pragma unroll
    for (int k = 1; k <= DEPTH; ++k) {
        int slot = k & (DEPTH - 1);
        uint32_t d0 = ring_base + ((slot * EPW + 0) * C_) * 4 + lane * 16;
        uint32_t d1 = ring_base + ((slot * EPW + 1) * C_) * 4 + lane * 16;
        cp16(d0, row0 + (size_t)k * C_ + lane * 4);
        cp16(d1, row1 + (size_t)k * C_ + lane * 4);
        CP_COMMIT();
    }

    // ---- t = 0 init (tiny direct loads by lanes 0/1)
    float aLo0 = 0.f, aHi0 = 0.f, aTop0 = 0.f;
    float aLo1 = 0.f, aHi1 = 0.f, aTop1 = 0.f;
    if (lane == 0) { aLo0 = row0[BLANK] + EPSF;  aLo1 = row1[BLANK] + EPSF; }
    if (lane == 1) { aLo0 = row0[extLo0] + EPSF; aLo1 = row1[extLo1] + EPSF; }

    float r0 = aLo0, r1 = aLo1;
    #pragma unroll
    for (int d = 16; d; d >>= 1) {
        r0 += __shfl_xor_sync(FULLMASK, r0, d);
        r1 += __shfl_xor_sync(FULLMASK, r1, d);
    }
    float acc0 = __logf(r0),            acc1 = __logf(r1);
    float pend0 = __fdividef(1.0f, r0), pend1 = __fdividef(1.0f, r1);

    // ---- gather row 1 probs ahead of the loop
    CP_WAIT7();
    __syncwarp();
    const float* s1e0 = &ring[1][0][0];
    const float* s1e1 = &ring[1][1][0];
    float cLo0 = s1e0[extLo0], cHi0 = s1e0[extHi0], cTp0 = s1e0[BLANK];
    float cLo1 = s1e1[extLo1], cHi1 = s1e1[extHi1], cTp1 = s1e1[BLANK];

    #pragma unroll 4
    for (int t = 1; t < T_; ++t) {
        // apply (possibly deferred) scale to the pre-gathered probs
        float ic0 = ((t & 3) == 2) ? pend0 : 1.0f;
        float ic1 = ((t & 3) == 2) ? pend1 : 1.0f;
        float e0 = EPSF * ic0, e1 = EPSF * ic1;
        float pLo0 = fmaf(cLo0, ic0, e0);
        float pHi0 = fmaf(cHi0, ic0, e0);
        float pTp0 = fmaf(cTp0, ic0, e0);
        float pLo1 = fmaf(cLo1, ic1, e1);
        float pHi1 = fmaf(cHi1, ic1, e1);
        float pTp1 = fmaf(cTp1, ic1, e1);

        // refill ring: row t+8 into slot t&7 (consumers of that slot are long done)
        int tn = (t + DEPTH < T_) ? (t + DEPTH) : (T_ - 1);
        int ws = t & (DEPTH - 1);
        uint32_t d0 = ring_base + ((ws * EPW + 0) * C_) * 4 + lane * 16;
        uint32_t d1 = ring_base + ((ws * EPW + 1) * C_) * 4 + lane * 16;
        cp16(d0, row0 + (size_t)tn * C_ + lane * 4);
        cp16(d1, row1 + (size_t)tn * C_ + lane * 4);
        CP_COMMIT();
        CP_WAIT7();          // row t+1 guaranteed complete
        __syncwarp();

        // gather probs for t+1 (overlaps the alpha chain below)
        int ts = (t + 1 < T_) ? (t + 1) : (T_ - 1);
        int gs = ts & (DEPTH - 1);
        const float* g0 = &ring[gs][0][0];
        const float* g1 = &ring[gs][1][0];
        cLo0 = g0[extLo0]; cHi0 = g0[extHi0]; cTp0 = g0[BLANK];
        cLo1 = g1[extLo1]; cHi1 = g1[extHi1]; cTp1 = g1[BLANK];

        // neighbor shifts (dead boundary values removed: they meet skip==0)
        float lo1a = __shfl_up_sync(FULLMASK, aLo0, 1);
        float lo2a = __shfl_up_sync(FULLMASK, aLo0, 2);
        float t31a = __shfl_sync(FULLMASK, aLo0, 31);
        float hi1a = __shfl_up_sync(FULLMASK, aHi0, 1);
        float hi2a = __shfl_up_sync(FULLMASK, aHi0, 2);
        float lo1b = __shfl_up_sync(FULLMASK, aLo1, 1);
        float lo2b = __shfl_up_sync(FULLMASK, aLo1, 2);
        float t31b = __shfl_sync(FULLMASK, aLo1, 31);
        float hi1b = __shfl_up_sync(FULLMASK, aHi1, 1);
        float hi2b = __shfl_up_sync(FULLMASK, aHi1, 2);
        if (lane == 0) { lo1a = 0.f; hi1a = t31a; lo1b = 0.f; hi1b = t31b; }
        if (lane == 1) { hi2a = t31a; hi2b = t31b; }

        float nLo0 = fmaf(skipLo0, lo2a, aLo0 + lo1a) * pLo0;
        float nHi0 = fmaf(skipHi0, hi2a, aHi0 + hi1a) * pHi0;
        float nTp0 = (aTop0 + aHi0) * pTp0;
        float nLo1 = fmaf(skipLo1, lo2b, aLo1 + lo1b) * pLo1;
        float nHi1 = fmaf(skipHi1, hi2b, aHi1 + hi1b) * pHi1;
        float nTp1 = (aTop1 + aHi1) * pTp1;
        aLo0 = nLo0; aHi0 = nHi0; aTop0 = nTp0;
        aLo1 = nLo1; aHi1 = nHi1; aTop1 = nTp1;

        // periodic rescale: reduce at t%4==0, result applied at t+2 (off critical path)
        if ((t & 3) == 0) {
            float s0 = nLo0 + nHi0 + ((lane == 31) ? nTp0 : 0.f);
            float s1 = nLo1 + nHi1 + ((lane == 31) ? nTp1 : 0.f);
            #pragma unroll
            for (int d = 16; d; d >>= 1) {
                s0 += __shfl_xor_sync(FULLMASK, s0, d);
                s1 += __shfl_xor_sync(FULLMASK, s1, d);
            }
            acc0 += __logf(s0);
            acc1 += __logf(s1);
            pend0 = __fdividef(1.0f, s0);
            pend1 = __fdividef(1.0f, s1);
        }
    }

    // loss = -( log(alpha[S-1] + alpha[S-2]) + sum of applied log-scales )
    if (lane == 31) {
        out[b0] = -(__logf(aTop0 + aHi0) + acc0);
        out[b1] = -(__logf(aTop1 + aHi1) + acc1);
    }
}

extern "C" void kernel_launch(void* const* d_in, const int* in_sizes, int n_in,
                              void* d_out, int out_size) {
    // Identify inputs by size: y_true has B*L elements, y_pred has B*T*C.
    int idx_small = 0, idx_big = 1;
    if (in_sizes[0] > in_sizes[1]) { idx_small = 1; idx_big = 0; }

    const int*   y_true = (const int*)d_in[idx_small];   // int32 view; width detected in-kernel
    const float* y_pred = (const float*)d_in[idx_big];
    float*       out    = (float*)d_out;

    int B = in_sizes[idx_big] / (T_ * C_);   // 1024
    int blocks = B / EPW;                    // 512 one-warp blocks -> all SMs busy
    ctc_alpha_kernel<<<blocks, 32>>>(y_true, y_pred, out);
}